// round 13
// baseline (speedup 1.0000x reference)
#include <cuda_runtime.h>

// Problem shape (fixed by setup_inputs): x (B=1024, S=1024, E=12), n_qubits = 12.
#define BB    1024
#define SSZ   1024
#define EE    12
#define EPSV  1e-5f
#define ROWS_PER_WARP 10   // 3 lanes per row, lanes 30-31 idle
#define SROWS  40          // rows per 128-thread block (4 warps)
#define NBY    32          // b-tiles (single-wave grid of 832 blocks)
#define NB     (BB / NBY)  // 32 b per block

// Scratch tables: attn[s][e], ffn[s][e]  (s in 0..1023, e in 0..11)
__device__ float g_attn[BB * EE];
__device__ float g_ffn [BB * EE];

// ---------------------------------------------------------------------------
// Kernel 1: per-row quantum "attention" and "ffn" tables (analytic collapse).
// One warp per j; 128 blocks x 256 threads.
// ---------------------------------------------------------------------------
__global__ __launch_bounds__(256) void qtb_k1(
    const float* __restrict__ x,
    const float* __restrict__ rxa,
    const float* __restrict__ rya,
    const float* __restrict__ wffn,   // (E, 12) row-major
    const float* __restrict__ bffn,
    const float* __restrict__ g1,
    const float* __restrict__ b1)
{
    __shared__ float s_attn12[12][12];            // attn rows 0..11 (for tok2)
    __shared__ __align__(16) float swx[8][148];   // per-warp x[j,0:12,0:12]
    __shared__ float scrx[12];

    const int tid  = threadIdx.x;
    const int warp = tid >> 5;
    const int lane = tid & 31;
    const int j    = blockIdx.x * 8 + warp;       // 0..1023

    if (tid < 12) scrx[tid] = __cosf(__ldg(&rxa[tid]));

    // Stage this warp's 144 contiguous floats (36 float4, coalesced)
    {
        const float4* xr = reinterpret_cast<const float4*>(x + (size_t)j * SSZ * EE);
        float4* sw = reinterpret_cast<float4*>(&swx[warp][0]);
        for (int t = lane; t < 36; t += 32) sw[t] = xr[t];
    }

    // Phase A0: attn rows 0..11 into smem (144 of 256 threads)
    if (tid < 144) {
        const int i = tid / 12;
        const int w = tid % 12;
        float z[12];
        #pragma unroll
        for (int k = 0; k < 12; k++)
            z[k] = __cosf(__ldg(&rxa[k])) * __cosf(__ldg(&x[(size_t)i * SSZ * EE + k * EE]));
        float p = 1.0f;
        if (w == 0) {
            #pragma unroll
            for (int k = 1; k < 12; k++) p *= z[k];
        } else {
            for (int k = 0; k <= w; k++) p *= z[k];
        }
        s_attn12[i][w] = p;
    }
    __syncthreads();

    // Phase A: this warp's own attn row (lane i holds z_i, shuffle products)
    float zl = 0.0f;
    if (lane < 12)
        zl = scrx[lane] * __cosf(swx[warp][lane * 12]);
    float aw = 1.0f;
    #pragma unroll
    for (int k = 0; k < 12; k++) {
        float zk = __shfl_sync(0xffffffffu, zl, k);
        bool incl = (lane == 0) ? (k >= 1) : (k <= lane);
        if (incl) aw *= zk;
    }
    if (lane < 12) g_attn[j * 12 + lane] = aw;

    // Phase B: lane i<12 computes tok2_i via the 12-wide LN of row (j,i)
    float r = 0.0f;
    if (lane < 12) {
        float v[12];
        float mu = 0.0f;
        #pragma unroll
        for (int e = 0; e < 12; e++) {
            v[e] = swx[warp][lane * 12 + e] + s_attn12[lane][e];
            mu  += v[e];
        }
        mu *= (1.0f / 12.0f);
        float var = 0.0f;
        #pragma unroll
        for (int e = 0; e < 12; e++) { float d = v[e] - mu; var += d * d; }
        var *= (1.0f / 12.0f);
        const float inv  = rsqrtf(var + EPSV);
        const float tok2 = (v[0] - mu) * inv * __ldg(&g1[0]) + __ldg(&b1[0]);
        r = fmaxf(__cosf(tok2 + __ldg(&rya[lane])), 0.0f);
    }

    // Phase C: ffn[j,e] = b_ffn[e] + sum_i r_i * w_ffn[e,i]
    float acc = (lane < 12) ? __ldg(&bffn[lane]) : 0.0f;
    #pragma unroll
    for (int i = 0; i < 12; i++) {
        float ri = __shfl_sync(0xffffffffu, r, i);
        if (lane < 12) acc = fmaf(ri, __ldg(&wffn[lane * 12 + i]), acc);
    }
    if (lane < 12) g_ffn[j * 12 + lane] = acc;
}

// ---------------------------------------------------------------------------
// Kernel 2: out[b,s,:] = LN2( LN1(x[b,s,:] + attn[s,:]) + ffn[s,:] )
// 3-lanes-per-row dataflow kernel (no smem/barriers). LN variance in
// E[v^2]-mu^2 form: mean+variance reduce in ONE shuffle round per LN,
// dependency depth 2 rounds/iter instead of 4.
// grid (ceil(SSZ/SROWS)=26, NBY=32) = 832 blocks -> single wave.
// ---------------------------------------------------------------------------
__global__ __launch_bounds__(128) void qtb_k2(
    const float* __restrict__ x,
    const float* __restrict__ g1, const float* __restrict__ b1,
    const float* __restrict__ g2, const float* __restrict__ b2,
    float* __restrict__ out)
{
    const int tid  = threadIdx.x;
    const int warp = tid >> 5;
    const int lane = tid & 31;

    const int grp  = lane / 3;                  // 0..9 (10 for lanes 30,31)
    const int g0   = grp * 3;                   // first lane of group
    const int sloc = blockIdx.x * SROWS + warp * ROWS_PER_WARP + grp;
    const bool valid = (lane < 30) && (sloc < SSZ);
    const int srow = valid ? sloc : (SSZ - 1);  // clamp for safe loads
    const int e0   = (lane - g0) * 4;           // 0, 4, or 8

    // Per-lane slices (registers)
    const float4 an = *reinterpret_cast<const float4*>(&g_attn[srow * 12 + e0]);
    const float4 fn = *reinterpret_cast<const float4*>(&g_ffn [srow * 12 + e0]);
    const float4 w1 = __ldg(reinterpret_cast<const float4*>(g1 + e0));
    const float4 c1 = __ldg(reinterpret_cast<const float4*>(b1 + e0));
    const float4 w2 = __ldg(reinterpret_cast<const float4*>(g2 + e0));
    const float4 c2 = __ldg(reinterpret_cast<const float4*>(b2 + e0));
    // b1 + ffn prefused
    const float cfx = c1.x + fn.x, cfy = c1.y + fn.y;
    const float cfz = c1.z + fn.z, cfw = c1.w + fn.w;

    const int b0 = blockIdx.y * NB;
    const size_t bstride = (size_t)SSZ * EE;
    const float* xp = x   + ((size_t)b0 * SSZ + srow) * EE + e0;
    float*       op = out + ((size_t)b0 * SSZ + srow) * EE + e0;

    const unsigned FULL = 0xffffffffu;

    #pragma unroll 4
    for (int bi = 0; bi < NB; bi++, xp += bstride, op += bstride) {
        const float4 q = __ldg(reinterpret_cast<const float4*>(xp));

        // v = x + attn
        const float vx = q.x + an.x, vy = q.y + an.y;
        const float vz = q.z + an.z, vw = q.w + an.w;

        // One shuffle round: sum and sumsq together (independent shuffles)
        const float ps  = (vx + vy) + (vz + vw);
        float ps2 = vx * vx;
        ps2 = fmaf(vy, vy, ps2); ps2 = fmaf(vz, vz, ps2); ps2 = fmaf(vw, vw, ps2);
        const float tot  = __shfl_sync(FULL, ps,  g0) + __shfl_sync(FULL, ps,  g0 + 1)
                         + __shfl_sync(FULL, ps,  g0 + 2);
        const float tot2 = __shfl_sync(FULL, ps2, g0) + __shfl_sync(FULL, ps2, g0 + 1)
                         + __shfl_sync(FULL, ps2, g0 + 2);
        const float mu  = tot * (1.0f / 12.0f);
        const float var = fmaf(-mu, mu, tot2 * (1.0f / 12.0f));
        const float inv = rsqrtf(var + EPSV);

        // u = (v - mu)*inv*g1 + (b1 + ffn)
        const float ux = (vx - mu) * inv * w1.x + cfx;
        const float uy = (vy - mu) * inv * w1.y + cfy;
        const float uz = (vz - mu) * inv * w1.z + cfz;
        const float uw = (vw - mu) * inv * w1.w + cfw;

        // Second shuffle round: sum and sumsq of u
        const float ps3 = (ux + uy) + (uz + uw);
        float ps4 = ux * ux;
        ps4 = fmaf(uy, uy, ps4); ps4 = fmaf(uz, uz, ps4); ps4 = fmaf(uw, uw, ps4);
        const float tot3 = __shfl_sync(FULL, ps3, g0) + __shfl_sync(FULL, ps3, g0 + 1)
                         + __shfl_sync(FULL, ps3, g0 + 2);
        const float tot4 = __shfl_sync(FULL, ps4, g0) + __shfl_sync(FULL, ps4, g0 + 1)
                         + __shfl_sync(FULL, ps4, g0 + 2);
        const float mu2  = tot3 * (1.0f / 12.0f);
        const float var2 = fmaf(-mu2, mu2, tot4 * (1.0f / 12.0f));
        const float inv2 = rsqrtf(var2 + EPSV);

        float4 o;
        o.x = (ux - mu2) * inv2 * w2.x + c2.x;
        o.y = (uy - mu2) * inv2 * w2.y + c2.y;
        o.z = (uz - mu2) * inv2 * w2.z + c2.z;
        o.w = (uw - mu2) * inv2 * w2.w + c2.w;

        if (valid)
            __stcs(reinterpret_cast<float4*>(op), o);
    }
}

// ---------------------------------------------------------------------------
extern "C" void kernel_launch(void* const* d_in, const int* in_sizes, int n_in,
                              void* d_out, int out_size)
{
    const float* x    = (const float*)d_in[0];   // (1024, 1024, 12)
    const float* rxa  = (const float*)d_in[1];   // (12,)
    const float* rya  = (const float*)d_in[2];   // (12,)
    const float* wffn = (const float*)d_in[3];   // (12, 12)
    const float* bffn = (const float*)d_in[4];   // (12,)
    const float* g1   = (const float*)d_in[5];
    const float* b1   = (const float*)d_in[6];
    const float* g2   = (const float*)d_in[7];
    const float* b2   = (const float*)d_in[8];
    float* out = (float*)d_out;

    qtb_k1<<<BB / 8, 256>>>(x, rxa, rya, wffn, bffn, g1, b1);
    const int gx = (SSZ + SROWS - 1) / SROWS;   // 26
    qtb_k2<<<dim3(gx, NBY), 128>>>(x, g1, b1, g2, b2, out);
}

// round 14
// speedup vs baseline: 1.0903x; 1.0903x over previous
#include <cuda_runtime.h>

// Problem shape (fixed by setup_inputs): x (B=1024, S=1024, E=12), n_qubits = 12.
#define BB    1024
#define SSZ   1024
#define EE    12
#define EPSV  1e-5f
#define ROWS_PER_WARP 10   // 3 lanes per row, lanes 30-31 idle
#define SROWS  40          // rows per 128-thread block (4 warps)
#define NBY    64          // b-tiles (R10 best-bench config)
#define NB     (BB / NBY)  // 16 b per block

// Scratch tables: attn[s][e], ffn[s][e]  (s in 0..1023, e in 0..11)
__device__ float g_attn[BB * EE];
__device__ float g_ffn [BB * EE];

// ---------------------------------------------------------------------------
// Kernel 1: per-row quantum "attention" and "ffn" tables (analytic collapse).
// One warp per j; 128 blocks x 256 threads.
// ---------------------------------------------------------------------------
__global__ __launch_bounds__(256) void qtb_k1(
    const float* __restrict__ x,
    const float* __restrict__ rxa,
    const float* __restrict__ rya,
    const float* __restrict__ wffn,   // (E, 12) row-major
    const float* __restrict__ bffn,
    const float* __restrict__ g1,
    const float* __restrict__ b1)
{
    __shared__ float s_attn12[12][12];            // attn rows 0..11 (for tok2)
    __shared__ __align__(16) float swx[8][148];   // per-warp x[j,0:12,0:12]
    __shared__ float scrx[12];

    const int tid  = threadIdx.x;
    const int warp = tid >> 5;
    const int lane = tid & 31;
    const int j    = blockIdx.x * 8 + warp;       // 0..1023

    if (tid < 12) scrx[tid] = __cosf(__ldg(&rxa[tid]));

    // Stage this warp's 144 contiguous floats (36 float4, coalesced)
    {
        const float4* xr = reinterpret_cast<const float4*>(x + (size_t)j * SSZ * EE);
        float4* sw = reinterpret_cast<float4*>(&swx[warp][0]);
        for (int t = lane; t < 36; t += 32) sw[t] = xr[t];
    }

    // Phase A0: attn rows 0..11 into smem (144 of 256 threads)
    if (tid < 144) {
        const int i = tid / 12;
        const int w = tid % 12;
        float z[12];
        #pragma unroll
        for (int k = 0; k < 12; k++)
            z[k] = __cosf(__ldg(&rxa[k])) * __cosf(__ldg(&x[(size_t)i * SSZ * EE + k * EE]));
        float p = 1.0f;
        if (w == 0) {
            #pragma unroll
            for (int k = 1; k < 12; k++) p *= z[k];
        } else {
            for (int k = 0; k <= w; k++) p *= z[k];
        }
        s_attn12[i][w] = p;
    }
    __syncthreads();

    // Phase A: this warp's own attn row (lane i holds z_i, shuffle products)
    float zl = 0.0f;
    if (lane < 12)
        zl = scrx[lane] * __cosf(swx[warp][lane * 12]);
    float aw = 1.0f;
    #pragma unroll
    for (int k = 0; k < 12; k++) {
        float zk = __shfl_sync(0xffffffffu, zl, k);
        bool incl = (lane == 0) ? (k >= 1) : (k <= lane);
        if (incl) aw *= zk;
    }
    if (lane < 12) g_attn[j * 12 + lane] = aw;

    // Phase B: lane i<12 computes tok2_i via the 12-wide LN of row (j,i)
    float r = 0.0f;
    if (lane < 12) {
        float v[12];
        float mu = 0.0f;
        #pragma unroll
        for (int e = 0; e < 12; e++) {
            v[e] = swx[warp][lane * 12 + e] + s_attn12[lane][e];
            mu  += v[e];
        }
        mu *= (1.0f / 12.0f);
        float var = 0.0f;
        #pragma unroll
        for (int e = 0; e < 12; e++) { float d = v[e] - mu; var += d * d; }
        var *= (1.0f / 12.0f);
        const float inv  = rsqrtf(var + EPSV);
        const float tok2 = (v[0] - mu) * inv * __ldg(&g1[0]) + __ldg(&b1[0]);
        r = fmaxf(__cosf(tok2 + __ldg(&rya[lane])), 0.0f);
    }

    // Phase C: ffn[j,e] = b_ffn[e] + sum_i r_i * w_ffn[e,i]
    float acc = (lane < 12) ? __ldg(&bffn[lane]) : 0.0f;
    #pragma unroll
    for (int i = 0; i < 12; i++) {
        float ri = __shfl_sync(0xffffffffu, r, i);
        if (lane < 12) acc = fmaf(ri, __ldg(&wffn[lane * 12 + i]), acc);
    }
    if (lane < 12) g_ffn[j * 12 + lane] = acc;
}

// ---------------------------------------------------------------------------
// Kernel 2: out[b,s,:] = LN2( LN1(x[b,s,:] + attn[s,:]) + ffn[s,:] )
// 3-lanes-per-row dataflow kernel (no smem/barriers). Reductions use
// own-value + 2 rotation shuffles (8 SHFL/iter instead of 12); variance in
// E[v^2]-mu^2 form (1 shuffle round per LN). Software-pipelined x loads.
// grid (ceil(SSZ/SROWS)=26, NBY=64), 128 threads.
// ---------------------------------------------------------------------------
__global__ __launch_bounds__(128) void qtb_k2(
    const float* __restrict__ x,
    const float* __restrict__ g1, const float* __restrict__ b1,
    const float* __restrict__ g2, const float* __restrict__ b2,
    float* __restrict__ out)
{
    const int tid  = threadIdx.x;
    const int warp = tid >> 5;
    const int lane = tid & 31;

    const int grp  = lane / 3;                  // 0..9 (10 for lanes 30,31)
    const int g0   = grp * 3;                   // first lane of group
    const int lid3 = lane - g0;                 // 0..2 within group
    // Rotation sources: the OTHER two lanes of this group (clamped for 30/31)
    const int sA = min(g0 + ((lid3 + 1) % 3), 31);
    const int sB = min(g0 + ((lid3 + 2) % 3), 31);

    const int sloc = blockIdx.x * SROWS + warp * ROWS_PER_WARP + grp;
    const bool valid = (lane < 30) && (sloc < SSZ);
    const int srow = valid ? sloc : (SSZ - 1);  // clamp for safe loads
    const int e0   = lid3 * 4;                  // 0, 4, or 8

    // Per-lane slices (registers)
    const float4 an = *reinterpret_cast<const float4*>(&g_attn[srow * 12 + e0]);
    const float4 fn = *reinterpret_cast<const float4*>(&g_ffn [srow * 12 + e0]);
    const float4 w1 = __ldg(reinterpret_cast<const float4*>(g1 + e0));
    const float4 c1 = __ldg(reinterpret_cast<const float4*>(b1 + e0));
    const float4 w2 = __ldg(reinterpret_cast<const float4*>(g2 + e0));
    const float4 c2 = __ldg(reinterpret_cast<const float4*>(b2 + e0));
    // b1 + ffn prefused
    const float cfx = c1.x + fn.x, cfy = c1.y + fn.y;
    const float cfz = c1.z + fn.z, cfw = c1.w + fn.w;

    const int b0 = blockIdx.y * NB;
    const size_t bstride = (size_t)SSZ * EE;
    const float* xp = x   + ((size_t)b0 * SSZ + srow) * EE + e0;
    float*       op = out + ((size_t)b0 * SSZ + srow) * EE + e0;

    const unsigned FULL = 0xffffffffu;

    // Software pipeline: q holds iter bi's data; fetch bi+1 before processing.
    float4 q = __ldg(reinterpret_cast<const float4*>(xp));

    #pragma unroll
    for (int bi = 0; bi < NB; bi++) {
        float4 qn;
        if (bi + 1 < NB)
            qn = __ldg(reinterpret_cast<const float4*>(xp + (bi + 1) * bstride));

        // v = x + attn
        const float vx = q.x + an.x, vy = q.y + an.y;
        const float vz = q.z + an.z, vw = q.w + an.w;

        // One shuffle round: sum and sumsq together; own + 2 rotations
        const float ps  = (vx + vy) + (vz + vw);
        float ps2 = vx * vx;
        ps2 = fmaf(vy, vy, ps2); ps2 = fmaf(vz, vz, ps2); ps2 = fmaf(vw, vw, ps2);
        const float tot  = ps  + __shfl_sync(FULL, ps,  sA) + __shfl_sync(FULL, ps,  sB);
        const float tot2 = ps2 + __shfl_sync(FULL, ps2, sA) + __shfl_sync(FULL, ps2, sB);
        const float mu  = tot * (1.0f / 12.0f);
        const float var = fmaf(-mu, mu, tot2 * (1.0f / 12.0f));
        const float inv = rsqrtf(var + EPSV);

        // u = (v - mu)*inv*g1 + (b1 + ffn)
        const float ux = (vx - mu) * inv * w1.x + cfx;
        const float uy = (vy - mu) * inv * w1.y + cfy;
        const float uz = (vz - mu) * inv * w1.z + cfz;
        const float uw = (vw - mu) * inv * w1.w + cfw;

        // Second shuffle round
        const float ps3 = (ux + uy) + (uz + uw);
        float ps4 = ux * ux;
        ps4 = fmaf(uy, uy, ps4); ps4 = fmaf(uz, uz, ps4); ps4 = fmaf(uw, uw, ps4);
        const float tot3 = ps3 + __shfl_sync(FULL, ps3, sA) + __shfl_sync(FULL, ps3, sB);
        const float tot4 = ps4 + __shfl_sync(FULL, ps4, sA) + __shfl_sync(FULL, ps4, sB);
        const float mu2  = tot3 * (1.0f / 12.0f);
        const float var2 = fmaf(-mu2, mu2, tot4 * (1.0f / 12.0f));
        const float inv2 = rsqrtf(var2 + EPSV);

        float4 o;
        o.x = (ux - mu2) * inv2 * w2.x + c2.x;
        o.y = (uy - mu2) * inv2 * w2.y + c2.y;
        o.z = (uz - mu2) * inv2 * w2.z + c2.z;
        o.w = (uw - mu2) * inv2 * w2.w + c2.w;

        if (valid)
            __stcs(reinterpret_cast<float4*>(op + bi * bstride), o);

        q = qn;
    }
}

// ---------------------------------------------------------------------------
extern "C" void kernel_launch(void* const* d_in, const int* in_sizes, int n_in,
                              void* d_out, int out_size)
{
    const float* x    = (const float*)d_in[0];   // (1024, 1024, 12)
    const float* rxa  = (const float*)d_in[1];   // (12,)
    const float* rya  = (const float*)d_in[2];   // (12,)
    const float* wffn = (const float*)d_in[3];   // (12, 12)
    const float* bffn = (const float*)d_in[4];   // (12,)
    const float* g1   = (const float*)d_in[5];
    const float* b1   = (const float*)d_in[6];
    const float* g2   = (const float*)d_in[7];
    const float* b2   = (const float*)d_in[8];
    float* out = (float*)d_out;

    qtb_k1<<<BB / 8, 256>>>(x, rxa, rya, wffn, bffn, g1, b1);
    const int gx = (SSZ + SROWS - 1) / SROWS;   // 26
    qtb_k2<<<dim3(gx, NBY), 128>>>(x, g1, b1, g2, b2, out);
}

// round 15
// speedup vs baseline: 1.1175x; 1.0250x over previous
#include <cuda_runtime.h>

// Problem shape (fixed by setup_inputs): x (B=1024, S=1024, E=12), n_qubits = 12.
#define BB    1024
#define SSZ   1024
#define EE    12
#define EPSV  1e-5f
#define ROWS_PER_WARP 10   // 3 lanes per row, lanes 30-31 idle
#define SROWS  40          // rows per 128-thread block (4 warps)
#define NBY    64          // b-tiles
#define NB     (BB / NBY)  // 16 b per block

// Scratch tables: attn[s][e], ffn[s][e]  (s in 0..1023, e in 0..11)
__device__ float g_attn[BB * EE];
__device__ float g_ffn [BB * EE];

// ---------------------------------------------------------------------------
// Kernel 1: per-row quantum "attention" and "ffn" tables (analytic collapse).
// One warp per j; 128 blocks x 256 threads.
// ---------------------------------------------------------------------------
__global__ __launch_bounds__(256) void qtb_k1(
    const float* __restrict__ x,
    const float* __restrict__ rxa,
    const float* __restrict__ rya,
    const float* __restrict__ wffn,   // (E, 12) row-major
    const float* __restrict__ bffn,
    const float* __restrict__ g1,
    const float* __restrict__ b1)
{
    __shared__ float s_attn12[12][12];            // attn rows 0..11 (for tok2)
    __shared__ __align__(16) float swx[8][148];   // per-warp x[j,0:12,0:12]
    __shared__ float scrx[12];

    const int tid  = threadIdx.x;
    const int warp = tid >> 5;
    const int lane = tid & 31;
    const int j    = blockIdx.x * 8 + warp;       // 0..1023

    if (tid < 12) scrx[tid] = __cosf(__ldg(&rxa[tid]));

    // Stage this warp's 144 contiguous floats (36 float4, coalesced)
    {
        const float4* xr = reinterpret_cast<const float4*>(x + (size_t)j * SSZ * EE);
        float4* sw = reinterpret_cast<float4*>(&swx[warp][0]);
        for (int t = lane; t < 36; t += 32) sw[t] = xr[t];
    }

    // Phase A0: attn rows 0..11 into smem (144 of 256 threads)
    if (tid < 144) {
        const int i = tid / 12;
        const int w = tid % 12;
        float z[12];
        #pragma unroll
        for (int k = 0; k < 12; k++)
            z[k] = __cosf(__ldg(&rxa[k])) * __cosf(__ldg(&x[(size_t)i * SSZ * EE + k * EE]));
        float p = 1.0f;
        if (w == 0) {
            #pragma unroll
            for (int k = 1; k < 12; k++) p *= z[k];
        } else {
            for (int k = 0; k <= w; k++) p *= z[k];
        }
        s_attn12[i][w] = p;
    }
    __syncthreads();

    // Phase A: this warp's own attn row (lane i holds z_i, shuffle products)
    float zl = 0.0f;
    if (lane < 12)
        zl = scrx[lane] * __cosf(swx[warp][lane * 12]);
    float aw = 1.0f;
    #pragma unroll
    for (int k = 0; k < 12; k++) {
        float zk = __shfl_sync(0xffffffffu, zl, k);
        bool incl = (lane == 0) ? (k >= 1) : (k <= lane);
        if (incl) aw *= zk;
    }
    if (lane < 12) g_attn[j * 12 + lane] = aw;

    // Phase B: lane i<12 computes tok2_i via the 12-wide LN of row (j,i)
    float r = 0.0f;
    if (lane < 12) {
        float v[12];
        float mu = 0.0f;
        #pragma unroll
        for (int e = 0; e < 12; e++) {
            v[e] = swx[warp][lane * 12 + e] + s_attn12[lane][e];
            mu  += v[e];
        }
        mu *= (1.0f / 12.0f);
        float var = 0.0f;
        #pragma unroll
        for (int e = 0; e < 12; e++) { float d = v[e] - mu; var += d * d; }
        var *= (1.0f / 12.0f);
        const float inv  = rsqrtf(var + EPSV);
        const float tok2 = (v[0] - mu) * inv * __ldg(&g1[0]) + __ldg(&b1[0]);
        r = fmaxf(__cosf(tok2 + __ldg(&rya[lane])), 0.0f);
    }

    // Phase C: ffn[j,e] = b_ffn[e] + sum_i r_i * w_ffn[e,i]
    float acc = (lane < 12) ? __ldg(&bffn[lane]) : 0.0f;
    #pragma unroll
    for (int i = 0; i < 12; i++) {
        float ri = __shfl_sync(0xffffffffu, r, i);
        if (lane < 12) acc = fmaf(ri, __ldg(&wffn[lane * 12 + i]), acc);
    }
    if (lane < 12) g_ffn[j * 12 + lane] = acc;
}

// ---------------------------------------------------------------------------
// Kernel 2: out[b,s,:] = LN2( LN1(x[b,s,:] + attn[s,:]) + ffn[s,:] )
// 3-lanes-per-row dataflow kernel (no smem/barriers). Per loop pass TWO
// b-values are processed with stage-interleaved chains (2x ILP hides the
// shuffle/MUFU latency); 8 SHFL per row via own+2 rotations; variance in
// E[v^2]-mu^2 form. Next pair's loads prefetched at pair start.
// grid (ceil(SSZ/SROWS)=26, NBY=64), 128 threads.
// ---------------------------------------------------------------------------
__global__ __launch_bounds__(128) void qtb_k2(
    const float* __restrict__ x,
    const float* __restrict__ g1, const float* __restrict__ b1,
    const float* __restrict__ g2, const float* __restrict__ b2,
    float* __restrict__ out)
{
    const int tid  = threadIdx.x;
    const int warp = tid >> 5;
    const int lane = tid & 31;

    const int grp  = lane / 3;                  // 0..9 (10 for lanes 30,31)
    const int g0   = grp * 3;                   // first lane of group
    const int lid3 = lane - g0;                 // 0..2 within group
    // Rotation sources: the OTHER two lanes of this group (clamped for 30/31)
    const int sA = min(g0 + ((lid3 + 1) % 3), 31);
    const int sB = min(g0 + ((lid3 + 2) % 3), 31);

    const int sloc = blockIdx.x * SROWS + warp * ROWS_PER_WARP + grp;
    const bool valid = (lane < 30) && (sloc < SSZ);
    const int srow = valid ? sloc : (SSZ - 1);  // clamp for safe loads
    const int e0   = lid3 * 4;                  // 0, 4, or 8

    // Per-lane slices (registers)
    const float4 an = *reinterpret_cast<const float4*>(&g_attn[srow * 12 + e0]);
    const float4 fn = *reinterpret_cast<const float4*>(&g_ffn [srow * 12 + e0]);
    const float4 w1 = __ldg(reinterpret_cast<const float4*>(g1 + e0));
    const float4 c1 = __ldg(reinterpret_cast<const float4*>(b1 + e0));
    const float4 w2 = __ldg(reinterpret_cast<const float4*>(g2 + e0));
    const float4 c2 = __ldg(reinterpret_cast<const float4*>(b2 + e0));
    // b1 + ffn prefused
    const float cfx = c1.x + fn.x, cfy = c1.y + fn.y;
    const float cfz = c1.z + fn.z, cfw = c1.w + fn.w;

    const int b0 = blockIdx.y * NB;
    const size_t bstride = (size_t)SSZ * EE;
    const float* xp = x   + ((size_t)b0 * SSZ + srow) * EE + e0;
    float*       op = out + ((size_t)b0 * SSZ + srow) * EE + e0;

    const unsigned FULL = 0xffffffffu;

    // Pair-pipelined: qa/qb hold rows bi, bi+1.
    float4 qa = __ldg(reinterpret_cast<const float4*>(xp));
    float4 qb = __ldg(reinterpret_cast<const float4*>(xp + bstride));

    #pragma unroll
    for (int p = 0; p < NB / 2; p++) {
        const int bi = 2 * p;
        float4 na, nb;
        if (p + 1 < NB / 2) {
            na = __ldg(reinterpret_cast<const float4*>(xp + (bi + 2) * bstride));
            nb = __ldg(reinterpret_cast<const float4*>(xp + (bi + 3) * bstride));
        }

        // ---- stage 1: v = x + attn (both chains) ----
        const float vxA = qa.x + an.x, vyA = qa.y + an.y;
        const float vzA = qa.z + an.z, vwA = qa.w + an.w;
        const float vxB = qb.x + an.x, vyB = qb.y + an.y;
        const float vzB = qb.z + an.z, vwB = qb.w + an.w;

        // ---- stage 2: partial sums, shuffle round 1 (interleaved) ----
        const float psA = (vxA + vyA) + (vzA + vwA);
        const float psB = (vxB + vyB) + (vzB + vwB);
        float p2A = vxA * vxA;
        p2A = fmaf(vyA, vyA, p2A); p2A = fmaf(vzA, vzA, p2A); p2A = fmaf(vwA, vwA, p2A);
        float p2B = vxB * vxB;
        p2B = fmaf(vyB, vyB, p2B); p2B = fmaf(vzB, vzB, p2B); p2B = fmaf(vwB, vwB, p2B);

        const float totA  = psA + __shfl_sync(FULL, psA, sA) + __shfl_sync(FULL, psA, sB);
        const float totB  = psB + __shfl_sync(FULL, psB, sA) + __shfl_sync(FULL, psB, sB);
        const float tot2A = p2A + __shfl_sync(FULL, p2A, sA) + __shfl_sync(FULL, p2A, sB);
        const float tot2B = p2B + __shfl_sync(FULL, p2B, sA) + __shfl_sync(FULL, p2B, sB);

        const float muA  = totA * (1.0f / 12.0f);
        const float muB  = totB * (1.0f / 12.0f);
        const float varA = fmaf(-muA, muA, tot2A * (1.0f / 12.0f));
        const float varB = fmaf(-muB, muB, tot2B * (1.0f / 12.0f));
        const float invA = rsqrtf(varA + EPSV);
        const float invB = rsqrtf(varB + EPSV);

        // ---- stage 3: u = (v - mu)*inv*g1 + (b1 + ffn) (both chains) ----
        const float uxA = (vxA - muA) * invA * w1.x + cfx;
        const float uyA = (vyA - muA) * invA * w1.y + cfy;
        const float uzA = (vzA - muA) * invA * w1.z + cfz;
        const float uwA = (vwA - muA) * invA * w1.w + cfw;
        const float uxB = (vxB - muB) * invB * w1.x + cfx;
        const float uyB = (vyB - muB) * invB * w1.y + cfy;
        const float uzB = (vzB - muB) * invB * w1.z + cfz;
        const float uwB = (vwB - muB) * invB * w1.w + cfw;

        // ---- stage 4: shuffle round 2 (interleaved) ----
        const float ps3A = (uxA + uyA) + (uzA + uwA);
        const float ps3B = (uxB + uyB) + (uzB + uwB);
        float p4A = uxA * uxA;
        p4A = fmaf(uyA, uyA, p4A); p4A = fmaf(uzA, uzA, p4A); p4A = fmaf(uwA, uwA, p4A);
        float p4B = uxB * uxB;
        p4B = fmaf(uyB, uyB, p4B); p4B = fmaf(uzB, uzB, p4B); p4B = fmaf(uwB, uwB, p4B);

        const float tot3A = ps3A + __shfl_sync(FULL, ps3A, sA) + __shfl_sync(FULL, ps3A, sB);
        const float tot3B = ps3B + __shfl_sync(FULL, ps3B, sA) + __shfl_sync(FULL, ps3B, sB);
        const float tot4A = p4A + __shfl_sync(FULL, p4A, sA) + __shfl_sync(FULL, p4A, sB);
        const float tot4B = p4B + __shfl_sync(FULL, p4B, sA) + __shfl_sync(FULL, p4B, sB);

        const float mu2A  = tot3A * (1.0f / 12.0f);
        const float mu2B  = tot3B * (1.0f / 12.0f);
        const float var2A = fmaf(-mu2A, mu2A, tot4A * (1.0f / 12.0f));
        const float var2B = fmaf(-mu2B, mu2B, tot4B * (1.0f / 12.0f));
        const float inv2A = rsqrtf(var2A + EPSV);
        const float inv2B = rsqrtf(var2B + EPSV);

        // ---- stage 5: outputs ----
        float4 oA, oB;
        oA.x = (uxA - mu2A) * inv2A * w2.x + c2.x;
        oA.y = (uyA - mu2A) * inv2A * w2.y + c2.y;
        oA.z = (uzA - mu2A) * inv2A * w2.z + c2.z;
        oA.w = (uwA - mu2A) * inv2A * w2.w + c2.w;
        oB.x = (uxB - mu2B) * inv2B * w2.x + c2.x;
        oB.y = (uyB - mu2B) * inv2B * w2.y + c2.y;
        oB.z = (uzB - mu2B) * inv2B * w2.z + c2.z;
        oB.w = (uwB - mu2B) * inv2B * w2.w + c2.w;

        if (valid) {
            __stcs(reinterpret_cast<float4*>(op + bi * bstride), oA);
            __stcs(reinterpret_cast<float4*>(op + (bi + 1) * bstride), oB);
        }

        qa = na;
        qb = nb;
    }
}

// ---------------------------------------------------------------------------
extern "C" void kernel_launch(void* const* d_in, const int* in_sizes, int n_in,
                              void* d_out, int out_size)
{
    const float* x    = (const float*)d_in[0];   // (1024, 1024, 12)
    const float* rxa  = (const float*)d_in[1];   // (12,)
    const float* rya  = (const float*)d_in[2];   // (12,)
    const float* wffn = (const float*)d_in[3];   // (12, 12)
    const float* bffn = (const float*)d_in[4];   // (12,)
    const float* g1   = (const float*)d_in[5];
    const float* b1   = (const float*)d_in[6];
    const float* g2   = (const float*)d_in[7];
    const float* b2   = (const float*)d_in[8];
    float* out = (float*)d_out;

    qtb_k1<<<BB / 8, 256>>>(x, rxa, rya, wffn, bffn, g1, b1);
    const int gx = (SSZ + SROWS - 1) / SROWS;   // 26
    qtb_k2<<<dim3(gx, NBY), 128>>>(x, g1, b1, g2, b2, out);
}